// round 7
// baseline (speedup 1.0000x reference)
#include <cuda_runtime.h>
#include <cuda_bf16.h>
#include <math.h>
#include <stdint.h>

// ---------------- problem constants (fixed by dataset) ----------------
#define B_     8
#define T2_    27
#define T3_    9
#define P_     17
#define C_     128
#define BT2_   216
#define LQ_    153
#define LV_    4080
#define NH_    8
#define NL_    4
#define NP_    4
#define DH_    16
#define NROWS_ (BT2_*LQ_)     // 33048
#define MVAL_  (BT2_*LV_)     // 881280
#define NEWQ_SIZE_ ((size_t)NROWS_*C_)
#define NOFF_  256
#define NCAT_  384

// ---------------- scratch ----------------
__device__ float g_offatt[(size_t)NROWS_ * NCAT_];
__device__ float g_samp[(size_t)NROWS_ * C_];
__device__ float g_bcat[NCAT_];
// bf16 hi/lo weight images, XOR-swizzled [n][k] layout, 5 chunks of 128x128:
// 0: W_val, 1: W_off[0:128), 2: W_off[128:256), 3: W_attn, 4: W_out
__device__ uint32_t g_wb_hi[5 * 8192];
__device__ uint32_t g_wb_lo[5 * 8192];

__device__ __forceinline__ uint32_t smem_u32(const void* p) {
    uint32_t a;
    asm("{ .reg .u64 t; cvta.to.shared.u64 t, %1; cvt.u32.u64 %0, t; }" : "=r"(a) : "l"(p));
    return a;
}

// swizzled byte offset within a 256B row: c = byte col (0..255), rm = row & 7
__device__ __forceinline__ uint32_t swz(uint32_t c, uint32_t rm) {
    return (c & 15u) | ((((c >> 4) ^ rm) & 15u) << 4);
}

// ---------------- prep: build all 5 weight-chunk hi/lo images ----------------
__global__ void prep_images(const float* __restrict__ W_val,
                            const float* __restrict__ W_off,
                            const float* __restrict__ W_attn,
                            const float* __restrict__ W_out)
{
    const float* srcs[5] = {W_val, W_off, W_off + 16384, W_attn, W_out};
    const float* W = srcs[blockIdx.x];
    unsigned short* hi = (unsigned short*)(g_wb_hi + blockIdx.x * 8192);
    unsigned short* lo = (unsigned short*)(g_wb_lo + blockIdx.x * 8192);
    for (int i = threadIdx.x; i < 16384; i += 256) {
        int n = i >> 7, k = i & 127;
        float w = W[i];
        __nv_bfloat16 h = __float2bfloat16_rn(w);
        float wl = w - __bfloat162float(h);
        __nv_bfloat16 l = __float2bfloat16_rn(wl);
        uint32_t byte = (uint32_t)n * 256u + swz((uint32_t)k * 2u, (uint32_t)(n & 7));
        hi[byte >> 1] = __bfloat16_as_ushort(h);
        lo[byte >> 1] = __bfloat16_as_ushort(l);
    }
}

__global__ void concat_bias(const float* __restrict__ boff, const float* __restrict__ battn) {
    int i = threadIdx.x;
    if (i < NCAT_) g_bcat[i] = (i < NOFF_) ? boff[i] : battn[i - NOFF_];
}

// ---------------- ldmatrix / mma helpers ----------------
#define LDSM4(r0, r1, r2, r3, addr) \
    asm volatile("ldmatrix.sync.aligned.m8n8.x4.shared.b16 {%0,%1,%2,%3}, [%4];" \
                 : "=r"(r0), "=r"(r1), "=r"(r2), "=r"(r3) : "r"(addr))

#define MMA16816(c, a, b0, b1) \
    asm volatile("mma.sync.aligned.m16n8k16.row.col.f32.bf16.bf16.f32 " \
                 "{%0,%1,%2,%3},{%4,%5,%6,%7},{%8,%9},{%0,%1,%2,%3};" \
                 : "+f"((c)[0]), "+f"((c)[1]), "+f"((c)[2]), "+f"((c)[3]) \
                 : "r"((a)[0]), "r"((a)[1]), "r"((a)[2]), "r"((a)[3]), "r"(b0), "r"(b1))

// ---------------- unified HMMA bf16 3-term-split GEMM ----------------
// CTA: 256 threads (8 warps), tile 256(M) x 128(N), K = 128.
// Warp layout 4(m) x 2(n): each warp computes 64x64 -> per warp per k-step
// 16 LDSM.x4 feed 96 MMAs (vs 12:48 before) => 1.5x less smem per MAC.
// blockIdx.y selects the 128-col weight chunk. Persistent over M-tiles.
// smem: A_hi 64KB | A_lo 64KB | B_hi 32KB | B_lo 32KB = 192KB, 1 CTA/SM.
#define CTM 256
#define VP_SMEM 196608
#define AHI_OFF 0
#define ALO_OFF 65536
#define BHI_OFF 131072
#define BLO_OFF 163840

__global__ __launch_bounds__(256, 1)
void hmma_gemm(const float* __restrict__ A,
               const uint32_t* __restrict__ wimg_hi_base,
               const uint32_t* __restrict__ wimg_lo_base,
               const float* __restrict__ bias_base,
               float* __restrict__ Out,
               int M, int ldout, int mtiles)
{
    extern __shared__ char sm[];
    const uint32_t sbase = smem_u32(sm);
    const int tid = threadIdx.x;
    const int wid = tid >> 5;
    const int lane = tid & 31;
    const int wm = wid >> 1;         // m quarter (64 rows)
    const int wn = wid & 1;          // n half (64 cols)
    const int colbase = blockIdx.y * 128;
    const float* bias = bias_base + colbase;

    // copy this chunk's pre-swizzled W images into smem (once)
    {
        const float4* shi = (const float4*)(wimg_hi_base + blockIdx.y * 8192);
        const float4* slo = (const float4*)(wimg_lo_base + blockIdx.y * 8192);
        float4* dhi = (float4*)(sm + BHI_OFF);
        float4* dlo = (float4*)(sm + BLO_OFF);
#pragma unroll
        for (int i = 0; i < 8; i++) {
            dhi[tid + i * 256] = shi[tid + i * 256];
            dlo[tid + i * 256] = slo[tid + i * 256];
        }
    }

    // fragment addressing (loop-invariant)
    const int sel = lane >> 3;            // 0..3
    const int li  = lane & 7;
    const int achunkbit = sel >> 1;
    // four m-sub-bands per warp: rows wm*64 + s*16
    uint32_t aHiB[4], aLoB[4];
#pragma unroll
    for (int s = 0; s < 4; s++) {
        int arow = wm * 64 + s * 16 + li + (sel & 1) * 8;
        aHiB[s] = sbase + AHI_OFF + (uint32_t)arow * 256u;
        aLoB[s] = sbase + ALO_OFF + (uint32_t)arow * 256u;
    }

    const int bchunkbit = sel & 1;
    const int bro = (sel >> 1) * 8 + li;
    uint32_t bHiBase[4], bLoBase[4];
#pragma unroll
    for (int g = 0; g < 4; g++) {
        uint32_t nrow = (uint32_t)(wn * 64 + g * 16 + bro);
        bHiBase[g] = sbase + BHI_OFF + nrow * 256u;
        bLoBase[g] = sbase + BLO_OFF + nrow * 256u;
    }

    // conversion: one row per thread
    char* phi = sm + AHI_OFF + tid * 256;
    char* plo = sm + ALO_OFF + tid * 256;
    const uint32_t crm = (uint32_t)(tid & 7);

    for (int tile = blockIdx.x; tile < mtiles; tile += gridDim.x) {
        const int bm = tile * CTM;
        __syncthreads();   // prior readers done / W copy done (iter 0)

        // convert this tile's 256x128 A rows into hi/lo bf16 swizzled tiles
        {
            const int grow = bm + tid;
            const bool valid = grow < M;
            const float4* src = (const float4*)(A + (size_t)grow * 128);
#pragma unroll
            for (int j4 = 0; j4 < 32; j4++) {
                float4 v = valid ? src[j4] : make_float4(0.f, 0.f, 0.f, 0.f);
                uint32_t c0 = (uint32_t)(j4 * 8);
                uint32_t s0 = swz(c0, crm);
                uint32_t s1 = s0 + 4;
                uint32_t h0, h1, l0, l1;
                asm("cvt.rn.bf16x2.f32 %0, %1, %2;" : "=r"(h0) : "f"(v.y), "f"(v.x));
                asm("cvt.rn.bf16x2.f32 %0, %1, %2;" : "=r"(h1) : "f"(v.w), "f"(v.z));
                float ah0 = __uint_as_float(h0 << 16);
                float ah1 = __uint_as_float(h0 & 0xffff0000u);
                float ah2 = __uint_as_float(h1 << 16);
                float ah3 = __uint_as_float(h1 & 0xffff0000u);
                asm("cvt.rn.bf16x2.f32 %0, %1, %2;" : "=r"(l0) : "f"(v.y - ah1), "f"(v.x - ah0));
                asm("cvt.rn.bf16x2.f32 %0, %1, %2;" : "=r"(l1) : "f"(v.w - ah3), "f"(v.z - ah2));
                *(uint32_t*)(phi + s0) = h0;
                *(uint32_t*)(phi + s1) = h1;
                *(uint32_t*)(plo + s0) = l0;
                *(uint32_t*)(plo + s1) = l1;
            }
        }
        __syncthreads();

        float c[4][8][4];
#pragma unroll
        for (int s = 0; s < 4; s++)
#pragma unroll
            for (int t = 0; t < 8; t++)
#pragma unroll
                for (int j = 0; j < 4; j++) c[s][t][j] = 0.f;

#pragma unroll
        for (int kk = 0; kk < 8; kk++) {
            uint32_t offA = (uint32_t)(((kk * 2 + achunkbit) ^ li) << 4);
            uint32_t offB = (uint32_t)(((kk * 2 + bchunkbit) ^ li) << 4);

            uint32_t ah[4][4], al[4][4];
#pragma unroll
            for (int s = 0; s < 4; s++) {
                LDSM4(ah[s][0], ah[s][1], ah[s][2], ah[s][3], aHiB[s] + offA);
                LDSM4(al[s][0], al[s][1], al[s][2], al[s][3], aLoB[s] + offA);
            }

#pragma unroll
            for (int g = 0; g < 4; g++) {
                uint32_t bh[4], bl[4];
                LDSM4(bh[0], bh[1], bh[2], bh[3], bHiBase[g] + offB);
                LDSM4(bl[0], bl[1], bl[2], bl[3], bLoBase[g] + offB);
                // hh across all 4 bands, then lh, then hl:
                // same-accumulator reuse distance = 8 MMAs
#pragma unroll
                for (int s = 0; s < 4; s++) {
                    MMA16816(c[s][2 * g],     ah[s], bh[0], bh[1]);
                    MMA16816(c[s][2 * g + 1], ah[s], bh[2], bh[3]);
                }
#pragma unroll
                for (int s = 0; s < 4; s++) {
                    MMA16816(c[s][2 * g],     al[s], bh[0], bh[1]);
                    MMA16816(c[s][2 * g + 1], al[s], bh[2], bh[3]);
                }
#pragma unroll
                for (int s = 0; s < 4; s++) {
                    MMA16816(c[s][2 * g],     ah[s], bl[0], bl[1]);
                    MMA16816(c[s][2 * g + 1], ah[s], bl[2], bl[3]);
                }
            }
        }

        // epilogue: bias + direct global stores
        {
            const int ncol = wn * 64 + 2 * (lane & 3);
#pragma unroll
            for (int s = 0; s < 4; s++) {
                const int m0 = bm + wm * 64 + s * 16 + (lane >> 2);
                const bool v0 = m0 < M;
                const bool v1 = (m0 + 8) < M;
                float* o0 = Out + (size_t)m0 * ldout + colbase;
                float* o1 = Out + (size_t)(m0 + 8) * ldout + colbase;
#pragma unroll
                for (int t = 0; t < 8; t++) {
                    int n = ncol + t * 8;
                    float2 bb = __ldg((const float2*)(bias + n));
                    if (v0) *(float2*)(o0 + n) = make_float2(c[s][t][0] + bb.x, c[s][t][1] + bb.y);
                    if (v1) *(float2*)(o1 + n) = make_float2(c[s][t][2] + bb.x, c[s][t][3] + bb.y);
                }
            }
        }
    }
}

// ---------------- deformable bilinear gather (softmax fused) ----------------
__global__ __launch_bounds__(128) void gather_kernel(
    const float* __restrict__ newv,
    const float* __restrict__ refp)
{
    int g = blockIdx.x * 4 + (threadIdx.x >> 5);
    int r = g >> 3;
    int h = g & 7;
    int lane = threadIdx.x & 31;
    int s = lane >> 1;           // sample 0..15
    int half = lane & 1;
    int l = s >> 2, p = s & 3;
    int b = r / LQ_;

    const int W = 48 >> l;
    const int H = 64 >> l;
    const int start = 4096 - (4096 >> (2 * l));

    int sidx = (h * 4 + l) * 4 + p;
    const float* orow = g_offatt + (size_t)r * NCAT_;
    float offx = orow[sidx * 2 + 0];
    float offy = orow[sidx * 2 + 1];

    // fused softmax over the 16 samples of this (r,h)
    float logit = orow[NOFF_ + h * 16 + s];
    float mx = logit;
#pragma unroll
    for (int m = 2; m <= 16; m <<= 1) mx = fmaxf(mx, __shfl_xor_sync(0xffffffffu, mx, m));
    float e = expf(logit - mx);
    float se = e;
#pragma unroll
    for (int m = 2; m <= 16; m <<= 1) se += __shfl_xor_sync(0xffffffffu, se, m);
    float aw = e / se;

    const float* rp = refp + ((size_t)r * 4 + l) * 2;
    float locx = rp[0] + offx / (float)W;
    float locy = rp[1] + offy / (float)H;
    float px = locx * (float)W - 0.5f;
    float py = locy * (float)H - 0.5f;
    float x0f = floorf(px), y0f = floorf(py);
    float fx = px - x0f, fy = py - y0f;
    int x0 = (int)x0f, y0 = (int)y0f;

    float cw00 = (1.f - fx) * (1.f - fy) * aw;
    float cw10 = fx * (1.f - fy) * aw;
    float cw01 = (1.f - fx) * fy * aw;
    float cw11 = fx * fy * aw;

    const float* base = newv + ((size_t)b * LV_ + start) * C_ + h * DH_ + half * 8;

    float acc[8] = {0.f, 0.f, 0.f, 0.f, 0.f, 0.f, 0.f, 0.f};
    auto corner = [&](int xi, int yi, float cw) {
        if ((unsigned)xi < (unsigned)W && (unsigned)yi < (unsigned)H) {
            const float4* vp = (const float4*)(base + ((size_t)yi * W + xi) * C_);
            float4 v0 = vp[0], v1 = vp[1];
            acc[0] += cw * v0.x; acc[1] += cw * v0.y;
            acc[2] += cw * v0.z; acc[3] += cw * v0.w;
            acc[4] += cw * v1.x; acc[5] += cw * v1.y;
            acc[6] += cw * v1.z; acc[7] += cw * v1.w;
        }
    };
    corner(x0,     y0,     cw00);
    corner(x0 + 1, y0,     cw10);
    corner(x0,     y0 + 1, cw01);
    corner(x0 + 1, y0 + 1, cw11);

#pragma unroll
    for (int m = 2; m <= 16; m <<= 1) {
#pragma unroll
        for (int i = 0; i < 8; i++)
            acc[i] += __shfl_xor_sync(0xffffffffu, acc[i], m);
    }

    if (s == 0) {
        float* dst = g_samp + (size_t)r * C_ + h * DH_ + half * 8;
        *(float4*)(dst + 0) = make_float4(acc[0], acc[1], acc[2], acc[3]);
        *(float4*)(dst + 4) = make_float4(acc[4], acc[5], acc[6], acc[7]);
    }
}

// ---------------- launch ----------------
extern "C" void kernel_launch(void* const* d_in, const int* in_sizes, int n_in,
                              void* d_out, int out_size)
{
    const float* query  = (const float*)d_in[0];
    const float* refp   = (const float*)d_in[1];
    const float* value  = (const float*)d_in[2];
    const float* W_off  = (const float*)d_in[5];
    const float* b_off  = (const float*)d_in[6];
    const float* W_attn = (const float*)d_in[7];
    const float* b_attn = (const float*)d_in[8];
    const float* W_val  = (const float*)d_in[9];
    const float* b_val  = (const float*)d_in[10];
    const float* W_out  = (const float*)d_in[11];
    const float* b_out  = (const float*)d_in[12];

    float* NEWQ = (float*)d_out;
    float* NEWV = NEWQ + NEWQ_SIZE_;

    float *p_offatt, *p_samp, *p_bcat;
    uint32_t *p_wb_hi, *p_wb_lo;
    cudaGetSymbolAddress((void**)&p_offatt, g_offatt);
    cudaGetSymbolAddress((void**)&p_samp,   g_samp);
    cudaGetSymbolAddress((void**)&p_bcat,   g_bcat);
    cudaGetSymbolAddress((void**)&p_wb_hi,  g_wb_hi);
    cudaGetSymbolAddress((void**)&p_wb_lo,  g_wb_lo);

    cudaFuncSetAttribute(hmma_gemm, cudaFuncAttributeMaxDynamicSharedMemorySize, VP_SMEM);

    // 1) prep weight images + bias concat
    prep_images<<<5, 256>>>(W_val, W_off, W_attn, W_out);
    concat_bias<<<1, NCAT_>>>(b_off, b_attn);

    // 2) value projection -> new_value (persistent: 148 CTAs, 1/SM)
    {
        int mtiles = (MVAL_ + CTM - 1) / CTM;   // 3443
        hmma_gemm<<<dim3(148, 1), 256, VP_SMEM>>>(
            value, p_wb_hi, p_wb_lo, b_val, NEWV, MVAL_, 128, mtiles);
    }

    // 3) offsets + attn logits (3 weight chunks: indices 1..3)
    {
        int mtiles = (NROWS_ + CTM - 1) / CTM;  // 130
        hmma_gemm<<<dim3(mtiles, 3), 256, VP_SMEM>>>(
            query, p_wb_hi + 8192, p_wb_lo + 8192, p_bcat, p_offatt, NROWS_, NCAT_, mtiles);
    }

    // 4) bilinear gather + fused softmax
    gather_kernel<<<NROWS_ * NH_ / 4, 128>>>(NEWV, refp);

    // 5) output projection -> new_query (chunk 4)
    {
        int mtiles = (NROWS_ + CTM - 1) / CTM;
        hmma_gemm<<<dim3(mtiles, 1), 256, VP_SMEM>>>(
            p_samp, p_wb_hi + 4 * 8192, p_wb_lo + 4 * 8192, b_out, NEWQ, NROWS_, 128, mtiles);
    }
}

// round 8
// speedup vs baseline: 1.2647x; 1.2647x over previous
#include <cuda_runtime.h>
#include <cuda_bf16.h>
#include <math.h>
#include <stdint.h>

// ---------------- problem constants (fixed by dataset) ----------------
#define B_     8
#define T2_    27
#define T3_    9
#define P_     17
#define C_     128
#define BT2_   216
#define LQ_    153
#define LV_    4080
#define NH_    8
#define NL_    4
#define NP_    4
#define DH_    16
#define NROWS_ (BT2_*LQ_)     // 33048
#define MVAL_  (BT2_*LV_)     // 881280
#define NEWQ_SIZE_ ((size_t)NROWS_*C_)
#define NOFF_  256
#define NCAT_  384

// ---------------- scratch ----------------
__device__ float g_offatt[(size_t)NROWS_ * NCAT_];
__device__ float g_samp[(size_t)NROWS_ * C_];
__device__ float g_bcat[NCAT_];
// bf16 hi/lo weight images, XOR-swizzled [n][k] layout, 5 chunks of 128x128:
// 0: W_val, 1: W_off[0:128), 2: W_off[128:256), 3: W_attn, 4: W_out
__device__ uint32_t g_wb_hi[5 * 8192];
__device__ uint32_t g_wb_lo[5 * 8192];

__device__ __forceinline__ uint32_t smem_u32(const void* p) {
    uint32_t a;
    asm("{ .reg .u64 t; cvta.to.shared.u64 t, %1; cvt.u32.u64 %0, t; }" : "=r"(a) : "l"(p));
    return a;
}

// swizzled byte offset within a 256B row: c = byte col (0..255), rm = row & 7
__device__ __forceinline__ uint32_t swz(uint32_t c, uint32_t rm) {
    return (c & 15u) | ((((c >> 4) ^ rm) & 15u) << 4);
}

// ---------------- prep: build all 5 weight-chunk hi/lo images ----------------
__global__ void prep_images(const float* __restrict__ W_val,
                            const float* __restrict__ W_off,
                            const float* __restrict__ W_attn,
                            const float* __restrict__ W_out)
{
    const float* srcs[5] = {W_val, W_off, W_off + 16384, W_attn, W_out};
    const float* W = srcs[blockIdx.x];
    unsigned short* hi = (unsigned short*)(g_wb_hi + blockIdx.x * 8192);
    unsigned short* lo = (unsigned short*)(g_wb_lo + blockIdx.x * 8192);
    for (int i = threadIdx.x; i < 16384; i += 256) {
        int n = i >> 7, k = i & 127;
        float w = W[i];
        __nv_bfloat16 h = __float2bfloat16_rn(w);
        float wl = w - __bfloat162float(h);
        __nv_bfloat16 l = __float2bfloat16_rn(wl);
        uint32_t byte = (uint32_t)n * 256u + swz((uint32_t)k * 2u, (uint32_t)(n & 7));
        hi[byte >> 1] = __bfloat16_as_ushort(h);
        lo[byte >> 1] = __bfloat16_as_ushort(l);
    }
}

__global__ void concat_bias(const float* __restrict__ boff, const float* __restrict__ battn) {
    int i = threadIdx.x;
    if (i < NCAT_) g_bcat[i] = (i < NOFF_) ? boff[i] : battn[i - NOFF_];
}

// ---------------- ldmatrix / mma helpers ----------------
#define LDSM4(r0, r1, r2, r3, addr) \
    asm volatile("ldmatrix.sync.aligned.m8n8.x4.shared.b16 {%0,%1,%2,%3}, [%4];" \
                 : "=r"(r0), "=r"(r1), "=r"(r2), "=r"(r3) : "r"(addr))

#define MMA16816(c, a, b0, b1) \
    asm volatile("mma.sync.aligned.m16n8k16.row.col.f32.bf16.bf16.f32 " \
                 "{%0,%1,%2,%3},{%4,%5,%6,%7},{%8,%9},{%0,%1,%2,%3};" \
                 : "+f"((c)[0]), "+f"((c)[1]), "+f"((c)[2]), "+f"((c)[3]) \
                 : "r"((a)[0]), "r"((a)[1]), "r"((a)[2]), "r"((a)[3]), "r"(b0), "r"(b1))

// convert float2 -> bf16x2 hi + residual-lo
__device__ __forceinline__ void split2(float2 v, uint32_t& h, uint32_t& l) {
    asm("cvt.rn.bf16x2.f32 %0, %1, %2;" : "=r"(h) : "f"(v.y), "f"(v.x));
    float hx = __uint_as_float(h << 16);
    float hy = __uint_as_float(h & 0xffff0000u);
    asm("cvt.rn.bf16x2.f32 %0, %1, %2;" : "=r"(l) : "f"(v.y - hy), "f"(v.x - hx));
}

// ---------------- unified HMMA bf16 3-term-split GEMM ----------------
// CTA: 128 threads (4 warps), tile 64(M) x 128(N), K = 128.
// Warp layout 2x2 (32(M) x 64(N) per warp).
// A is loaded DIRECTLY from global into MMA fragments (LDG.64) and converted
// to bf16 hi/lo in registers -- no A smem, no STS, no A-side LDSM, no
// per-tile __syncthreads. smem holds only the B hi/lo images (64 KB) ->
// 3 CTAs/SM, barrier-free mainloop.
#define CTM 64
#define VP_SMEM 65536
#define BHI_OFF 0
#define BLO_OFF 32768

__global__ __launch_bounds__(128, 3)
void hmma_gemm(const float* __restrict__ A,
               const uint32_t* __restrict__ wimg_hi_base,
               const uint32_t* __restrict__ wimg_lo_base,
               const float* __restrict__ bias_base,
               float* __restrict__ Out,
               int M, int ldout, int mtiles)
{
    extern __shared__ char sm[];
    const uint32_t sbase = smem_u32(sm);
    const int tid = threadIdx.x;
    const int wid = tid >> 5;
    const int lane = tid & 31;
    const int wm = wid & 1;          // m half (32 rows)
    const int wn = wid >> 1;         // n half (64 cols)
    const int colbase = blockIdx.y * 128;
    const float* bias = bias_base + colbase;

    // copy this chunk's pre-swizzled W images into smem (once)
    {
        const float4* shi = (const float4*)(wimg_hi_base + blockIdx.y * 8192);
        const float4* slo = (const float4*)(wimg_lo_base + blockIdx.y * 8192);
        float4* dhi = (float4*)(sm + BHI_OFF);
        float4* dlo = (float4*)(sm + BLO_OFF);
#pragma unroll
        for (int i = 0; i < 16; i++) {
            dhi[tid + i * 128] = shi[tid + i * 128];
            dlo[tid + i * 128] = slo[tid + i * 128];
        }
    }
    __syncthreads();   // only barrier in the kernel

    // B fragment addressing (loop-invariant)
    const int sel = lane >> 3;            // 0..3
    const int li  = lane & 7;
    const int bchunkbit = sel & 1;
    const int bro = (sel >> 1) * 8 + li;
    uint32_t bHiBase[4], bLoBase[4];
#pragma unroll
    for (int g = 0; g < 4; g++) {
        uint32_t nrow = (uint32_t)(wn * 64 + g * 16 + bro);
        bHiBase[g] = sbase + BHI_OFF + nrow * 256u;
        bLoBase[g] = sbase + BLO_OFF + nrow * 256u;
    }

    // A fragment addressing: lane -> (row offset, col offset) within 16x16 block
    const int ar = lane >> 2;             // 0..7
    const int ac = 2 * (lane & 3);        // 0,2,4,6

    for (int tile = blockIdx.x; tile < mtiles; tile += gridDim.x) {
        const int bm = tile * CTM;
        const int r0 = bm + wm * 32 + ar;

        float c[2][8][4];
#pragma unroll
        for (int s = 0; s < 2; s++)
#pragma unroll
            for (int t = 0; t < 8; t++)
#pragma unroll
                for (int j = 0; j < 4; j++) c[s][t][j] = 0.f;

#pragma unroll
        for (int kk = 0; kk < 8; kk++) {
            // A: direct global load + in-register bf16 split, per m-band
            uint32_t ah[2][4], al[2][4];
#pragma unroll
            for (int s = 0; s < 2; s++) {
                const int r = r0 + s * 16;
                const bool v0 = r < M;
                const bool v1 = (r + 8) < M;
                const float* p0 = A + (size_t)r * 128 + kk * 16 + ac;
                const float* p1 = p0 + 8 * 128;
                float2 f0 = v0 ? *(const float2*)(p0)     : make_float2(0.f, 0.f);
                float2 f1 = v1 ? *(const float2*)(p1)     : make_float2(0.f, 0.f);
                float2 f2 = v0 ? *(const float2*)(p0 + 8) : make_float2(0.f, 0.f);
                float2 f3 = v1 ? *(const float2*)(p1 + 8) : make_float2(0.f, 0.f);
                split2(f0, ah[s][0], al[s][0]);
                split2(f1, ah[s][1], al[s][1]);
                split2(f2, ah[s][2], al[s][2]);
                split2(f3, ah[s][3], al[s][3]);
            }

            const uint32_t offB = (uint32_t)(((kk * 2 + bchunkbit) ^ li) << 4);
#pragma unroll
            for (int g = 0; g < 4; g++) {
                uint32_t bh[4], bl[4];
                LDSM4(bh[0], bh[1], bh[2], bh[3], bHiBase[g] + offB);
                LDSM4(bl[0], bl[1], bl[2], bl[3], bLoBase[g] + offB);
#pragma unroll
                for (int s = 0; s < 2; s++) {
                    MMA16816(c[s][2 * g],     ah[s], bh[0], bh[1]);
                    MMA16816(c[s][2 * g + 1], ah[s], bh[2], bh[3]);
                    MMA16816(c[s][2 * g],     al[s], bh[0], bh[1]);
                    MMA16816(c[s][2 * g + 1], al[s], bh[2], bh[3]);
                    MMA16816(c[s][2 * g],     ah[s], bl[0], bl[1]);
                    MMA16816(c[s][2 * g + 1], ah[s], bl[2], bl[3]);
                }
            }
        }

        // epilogue: bias + direct global stores
        {
            const int ncol = wn * 64 + 2 * (lane & 3);
#pragma unroll
            for (int s = 0; s < 2; s++) {
                const int m0 = bm + wm * 32 + s * 16 + (lane >> 2);
                const bool v0 = m0 < M;
                const bool v1 = (m0 + 8) < M;
                float* o0 = Out + (size_t)m0 * ldout + colbase;
                float* o1 = Out + (size_t)(m0 + 8) * ldout + colbase;
#pragma unroll
                for (int t = 0; t < 8; t++) {
                    int n = ncol + t * 8;
                    float2 bb = __ldg((const float2*)(bias + n));
                    if (v0) *(float2*)(o0 + n) = make_float2(c[s][t][0] + bb.x, c[s][t][1] + bb.y);
                    if (v1) *(float2*)(o1 + n) = make_float2(c[s][t][2] + bb.x, c[s][t][3] + bb.y);
                }
            }
        }
    }
}

// ---------------- deformable bilinear gather (softmax fused) ----------------
__global__ __launch_bounds__(128) void gather_kernel(
    const float* __restrict__ newv,
    const float* __restrict__ refp)
{
    int g = blockIdx.x * 4 + (threadIdx.x >> 5);
    int r = g >> 3;
    int h = g & 7;
    int lane = threadIdx.x & 31;
    int s = lane >> 1;           // sample 0..15
    int half = lane & 1;
    int l = s >> 2, p = s & 3;
    int b = r / LQ_;

    const int W = 48 >> l;
    const int H = 64 >> l;
    const int start = 4096 - (4096 >> (2 * l));

    int sidx = (h * 4 + l) * 4 + p;
    const float* orow = g_offatt + (size_t)r * NCAT_;
    float offx = orow[sidx * 2 + 0];
    float offy = orow[sidx * 2 + 1];

    // fused softmax over the 16 samples of this (r,h)
    float logit = orow[NOFF_ + h * 16 + s];
    float mx = logit;
#pragma unroll
    for (int m = 2; m <= 16; m <<= 1) mx = fmaxf(mx, __shfl_xor_sync(0xffffffffu, mx, m));
    float e = expf(logit - mx);
    float se = e;
#pragma unroll
    for (int m = 2; m <= 16; m <<= 1) se += __shfl_xor_sync(0xffffffffu, se, m);
    float aw = e / se;

    const float* rp = refp + ((size_t)r * 4 + l) * 2;
    float locx = rp[0] + offx / (float)W;
    float locy = rp[1] + offy / (float)H;
    float px = locx * (float)W - 0.5f;
    float py = locy * (float)H - 0.5f;
    float x0f = floorf(px), y0f = floorf(py);
    float fx = px - x0f, fy = py - y0f;
    int x0 = (int)x0f, y0 = (int)y0f;

    float cw00 = (1.f - fx) * (1.f - fy) * aw;
    float cw10 = fx * (1.f - fy) * aw;
    float cw01 = (1.f - fx) * fy * aw;
    float cw11 = fx * fy * aw;

    const float* base = newv + ((size_t)b * LV_ + start) * C_ + h * DH_ + half * 8;

    float acc[8] = {0.f, 0.f, 0.f, 0.f, 0.f, 0.f, 0.f, 0.f};
    auto corner = [&](int xi, int yi, float cw) {
        if ((unsigned)xi < (unsigned)W && (unsigned)yi < (unsigned)H) {
            const float4* vp = (const float4*)(base + ((size_t)yi * W + xi) * C_);
            float4 v0 = vp[0], v1 = vp[1];
            acc[0] += cw * v0.x; acc[1] += cw * v0.y;
            acc[2] += cw * v0.z; acc[3] += cw * v0.w;
            acc[4] += cw * v1.x; acc[5] += cw * v1.y;
            acc[6] += cw * v1.z; acc[7] += cw * v1.w;
        }
    };
    corner(x0,     y0,     cw00);
    corner(x0 + 1, y0,     cw10);
    corner(x0,     y0 + 1, cw01);
    corner(x0 + 1, y0 + 1, cw11);

#pragma unroll
    for (int m = 2; m <= 16; m <<= 1) {
#pragma unroll
        for (int i = 0; i < 8; i++)
            acc[i] += __shfl_xor_sync(0xffffffffu, acc[i], m);
    }

    if (s == 0) {
        float* dst = g_samp + (size_t)r * C_ + h * DH_ + half * 8;
        *(float4*)(dst + 0) = make_float4(acc[0], acc[1], acc[2], acc[3]);
        *(float4*)(dst + 4) = make_float4(acc[4], acc[5], acc[6], acc[7]);
    }
}

// ---------------- launch ----------------
extern "C" void kernel_launch(void* const* d_in, const int* in_sizes, int n_in,
                              void* d_out, int out_size)
{
    const float* query  = (const float*)d_in[0];
    const float* refp   = (const float*)d_in[1];
    const float* value  = (const float*)d_in[2];
    const float* W_off  = (const float*)d_in[5];
    const float* b_off  = (const float*)d_in[6];
    const float* W_attn = (const float*)d_in[7];
    const float* b_attn = (const float*)d_in[8];
    const float* W_val  = (const float*)d_in[9];
    const float* b_val  = (const float*)d_in[10];
    const float* W_out  = (const float*)d_in[11];
    const float* b_out  = (const float*)d_in[12];

    float* NEWQ = (float*)d_out;
    float* NEWV = NEWQ + NEWQ_SIZE_;

    float *p_offatt, *p_samp, *p_bcat;
    uint32_t *p_wb_hi, *p_wb_lo;
    cudaGetSymbolAddress((void**)&p_offatt, g_offatt);
    cudaGetSymbolAddress((void**)&p_samp,   g_samp);
    cudaGetSymbolAddress((void**)&p_bcat,   g_bcat);
    cudaGetSymbolAddress((void**)&p_wb_hi,  g_wb_hi);
    cudaGetSymbolAddress((void**)&p_wb_lo,  g_wb_lo);

    cudaFuncSetAttribute(hmma_gemm, cudaFuncAttributeMaxDynamicSharedMemorySize, VP_SMEM);

    // 1) prep weight images + bias concat
    prep_images<<<5, 256>>>(W_val, W_off, W_attn, W_out);
    concat_bias<<<1, NCAT_>>>(b_off, b_attn);

    // 2) value projection -> new_value (persistent: 3 CTAs/SM x 148 SMs)
    {
        int mtiles = MVAL_ / CTM;               // 13770
        hmma_gemm<<<dim3(444, 1), 128, VP_SMEM>>>(
            value, p_wb_hi, p_wb_lo, b_val, NEWV, MVAL_, 128, mtiles);
    }

    // 3) offsets + attn logits (3 weight chunks: indices 1..3)
    {
        int mtiles = (NROWS_ + CTM - 1) / CTM;  // 517
        hmma_gemm<<<dim3(mtiles, 3), 128, VP_SMEM>>>(
            query, p_wb_hi + 8192, p_wb_lo + 8192, p_bcat, p_offatt, NROWS_, NCAT_, mtiles);
    }

    // 4) bilinear gather + fused softmax
    gather_kernel<<<NROWS_ * NH_ / 4, 128>>>(NEWV, refp);

    // 5) output projection -> new_query (chunk 4)
    {
        int mtiles = (NROWS_ + CTM - 1) / CTM;
        hmma_gemm<<<dim3(mtiles, 1), 128, VP_SMEM>>>(
            p_samp, p_wb_hi + 4 * 8192, p_wb_lo + 4 * 8192, b_out, NEWQ, NROWS_, 128, mtiles);
    }
}

// round 9
// speedup vs baseline: 1.4032x; 1.1095x over previous
#include <cuda_runtime.h>
#include <cuda_fp16.h>
#include <math.h>
#include <stdint.h>

// ---------------- problem constants (fixed by dataset) ----------------
#define B_     8
#define T2_    27
#define T3_    9
#define P_     17
#define C_     128
#define BT2_   216
#define LQ_    153
#define LV_    4080
#define NH_    8
#define NL_    4
#define NP_    4
#define DH_    16
#define NROWS_ (BT2_*LQ_)     // 33048
#define MVAL_  (BT2_*LV_)     // 881280
#define NEWQ_SIZE_ ((size_t)NROWS_*C_)
#define NOFF_  256
#define NCAT_  384

// ---------------- scratch ----------------
__device__ float g_offatt[(size_t)NROWS_ * NCAT_];
__device__ float g_samp[(size_t)NROWS_ * C_];
__device__ float g_bcat[NCAT_];
// fp16 weight images, XOR-swizzled [n][k] layout, 5 chunks of 128x128:
// 0: W_val, 1: W_off[0:128), 2: W_off[128:256), 3: W_attn, 4: W_out
__device__ uint32_t g_wb[5 * 8192];   // 32KB per chunk

__device__ __forceinline__ uint32_t smem_u32(const void* p) {
    uint32_t a;
    asm("{ .reg .u64 t; cvta.to.shared.u64 t, %1; cvt.u32.u64 %0, t; }" : "=r"(a) : "l"(p));
    return a;
}

// swizzled byte offset within a 256B row: c = byte col (0..255), rm = row & 7
__device__ __forceinline__ uint32_t swz(uint32_t c, uint32_t rm) {
    return (c & 15u) | ((((c >> 4) ^ rm) & 15u) << 4);
}

// ---------------- prep: build 5 fp16 weight-chunk images ----------------
__global__ void prep_images(const float* __restrict__ W_val,
                            const float* __restrict__ W_off,
                            const float* __restrict__ W_attn,
                            const float* __restrict__ W_out)
{
    const float* srcs[5] = {W_val, W_off, W_off + 16384, W_attn, W_out};
    const float* W = srcs[blockIdx.x];
    unsigned short* img = (unsigned short*)(g_wb + blockIdx.x * 8192);
    for (int i = threadIdx.x; i < 16384; i += 256) {
        int n = i >> 7, k = i & 127;
        __half h = __float2half_rn(W[i]);
        uint32_t byte = (uint32_t)n * 256u + swz((uint32_t)k * 2u, (uint32_t)(n & 7));
        img[byte >> 1] = *(unsigned short*)&h;
    }
}

__global__ void concat_bias(const float* __restrict__ boff, const float* __restrict__ battn) {
    int i = threadIdx.x;
    if (i < NCAT_) g_bcat[i] = (i < NOFF_) ? boff[i] : battn[i - NOFF_];
}

// ---------------- ldmatrix / mma helpers ----------------
#define LDSM4(r0, r1, r2, r3, addr) \
    asm volatile("ldmatrix.sync.aligned.m8n8.x4.shared.b16 {%0,%1,%2,%3}, [%4];" \
                 : "=r"(r0), "=r"(r1), "=r"(r2), "=r"(r3) : "r"(addr))

#define MMAH16816(c, a, b0, b1) \
    asm volatile("mma.sync.aligned.m16n8k16.row.col.f32.f16.f16.f32 " \
                 "{%0,%1,%2,%3},{%4,%5,%6,%7},{%8,%9},{%0,%1,%2,%3};" \
                 : "+f"((c)[0]), "+f"((c)[1]), "+f"((c)[2]), "+f"((c)[3]) \
                 : "r"((a)[0]), "r"((a)[1]), "r"((a)[2]), "r"((a)[3]), "r"(b0), "r"(b1))

// float2 -> fp16x2 hi + exact fp16x2 residual (a = h + l to ~22 bits)
__device__ __forceinline__ void split2h(float2 v, uint32_t& h, uint32_t& l) {
    __half2 hh = __floats2half2_rn(v.x, v.y);
    float2 hf = __half22float2(hh);
    __half2 ll = __floats2half2_rn(v.x - hf.x, v.y - hf.y);
    h = *(uint32_t*)&hh;
    l = *(uint32_t*)&ll;
}

// ---------------- unified HMMA fp16 2-term-split GEMM ----------------
// Out = A * W^T + bias.  A split to fp16 hi+lo in registers (exact),
// W rounded to fp16 (error 2^-12 rel -- the only precision loss).
// CTA: 128 threads (4 warps), tile 64(M) x 128(N), K = 128, warp 32x64.
// A loaded directly from global into fragments; smem holds only the fp16
// W image (32 KB). Barrier-free mainloop.
#define CTM 64
#define VP_SMEM 32768

__global__ __launch_bounds__(128, 3)
void hmma_gemm(const float* __restrict__ A,
               const uint32_t* __restrict__ wimg_base,
               const float* __restrict__ bias_base,
               float* __restrict__ Out,
               int M, int ldout, int mtiles)
{
    extern __shared__ char sm[];
    const uint32_t sbase = smem_u32(sm);
    const int tid = threadIdx.x;
    const int wid = tid >> 5;
    const int lane = tid & 31;
    const int wm = wid & 1;          // m half (32 rows)
    const int wn = wid >> 1;         // n half (64 cols)
    const int colbase = blockIdx.y * 128;
    const float* bias = bias_base + colbase;

    // copy this chunk's pre-swizzled fp16 W image into smem (once)
    {
        const float4* s4 = (const float4*)(wimg_base + blockIdx.y * 8192);
        float4* d4 = (float4*)sm;
#pragma unroll
        for (int i = 0; i < 16; i++) d4[tid + i * 128] = s4[tid + i * 128];
    }
    __syncthreads();   // only barrier in the kernel

    // B fragment addressing (loop-invariant)
    const int sel = lane >> 3;            // 0..3
    const int li  = lane & 7;
    const int bchunkbit = sel & 1;
    const int bro = (sel >> 1) * 8 + li;
    uint32_t bBase[4];
#pragma unroll
    for (int g = 0; g < 4; g++) {
        uint32_t nrow = (uint32_t)(wn * 64 + g * 16 + bro);
        bBase[g] = sbase + nrow * 256u;
    }

    // A fragment addressing
    const int ar = lane >> 2;             // 0..7
    const int ac = 2 * (lane & 3);        // 0,2,4,6

    for (int tile = blockIdx.x; tile < mtiles; tile += gridDim.x) {
        const int bm = tile * CTM;
        const int r0 = bm + wm * 32 + ar;

        float c[2][8][4];
#pragma unroll
        for (int s = 0; s < 2; s++)
#pragma unroll
            for (int t = 0; t < 8; t++)
#pragma unroll
                for (int j = 0; j < 4; j++) c[s][t][j] = 0.f;

#pragma unroll
        for (int kk = 0; kk < 8; kk++) {
            // A: direct global load + in-register fp16 split, per m-band
            uint32_t ah[2][4], al[2][4];
#pragma unroll
            for (int s = 0; s < 2; s++) {
                const int r = r0 + s * 16;
                const bool v0 = r < M;
                const bool v1 = (r + 8) < M;
                const float* p0 = A + (size_t)r * 128 + kk * 16 + ac;
                const float* p1 = p0 + 8 * 128;
                float2 f0 = v0 ? *(const float2*)(p0)     : make_float2(0.f, 0.f);
                float2 f1 = v1 ? *(const float2*)(p1)     : make_float2(0.f, 0.f);
                float2 f2 = v0 ? *(const float2*)(p0 + 8) : make_float2(0.f, 0.f);
                float2 f3 = v1 ? *(const float2*)(p1 + 8) : make_float2(0.f, 0.f);
                split2h(f0, ah[s][0], al[s][0]);
                split2h(f1, ah[s][1], al[s][1]);
                split2h(f2, ah[s][2], al[s][2]);
                split2h(f3, ah[s][3], al[s][3]);
            }

            const uint32_t offB = (uint32_t)(((kk * 2 + bchunkbit) ^ li) << 4);
#pragma unroll
            for (int g = 0; g < 4; g++) {
                uint32_t bh[4];
                LDSM4(bh[0], bh[1], bh[2], bh[3], bBase[g] + offB);
#pragma unroll
                for (int s = 0; s < 2; s++) {
                    MMAH16816(c[s][2 * g],     ah[s], bh[0], bh[1]);
                    MMAH16816(c[s][2 * g + 1], ah[s], bh[2], bh[3]);
                }
#pragma unroll
                for (int s = 0; s < 2; s++) {
                    MMAH16816(c[s][2 * g],     al[s], bh[0], bh[1]);
                    MMAH16816(c[s][2 * g + 1], al[s], bh[2], bh[3]);
                }
            }
        }

        // epilogue: bias + direct global stores
        {
            const int ncol = wn * 64 + 2 * (lane & 3);
#pragma unroll
            for (int s = 0; s < 2; s++) {
                const int m0 = bm + wm * 32 + s * 16 + (lane >> 2);
                const bool v0 = m0 < M;
                const bool v1 = (m0 + 8) < M;
                float* o0 = Out + (size_t)m0 * ldout + colbase;
                float* o1 = Out + (size_t)(m0 + 8) * ldout + colbase;
#pragma unroll
                for (int t = 0; t < 8; t++) {
                    int n = ncol + t * 8;
                    float2 bb = __ldg((const float2*)(bias + n));
                    if (v0) *(float2*)(o0 + n) = make_float2(c[s][t][0] + bb.x, c[s][t][1] + bb.y);
                    if (v1) *(float2*)(o1 + n) = make_float2(c[s][t][2] + bb.x, c[s][t][3] + bb.y);
                }
            }
        }
    }
}

// ---------------- deformable bilinear gather (softmax fused) ----------------
__global__ __launch_bounds__(128) void gather_kernel(
    const float* __restrict__ newv,
    const float* __restrict__ refp)
{
    int g = blockIdx.x * 4 + (threadIdx.x >> 5);
    int r = g >> 3;
    int h = g & 7;
    int lane = threadIdx.x & 31;
    int s = lane >> 1;           // sample 0..15
    int half = lane & 1;
    int l = s >> 2, p = s & 3;
    int b = r / LQ_;

    const int W = 48 >> l;
    const int H = 64 >> l;
    const int start = 4096 - (4096 >> (2 * l));

    int sidx = (h * 4 + l) * 4 + p;
    const float* orow = g_offatt + (size_t)r * NCAT_;
    float offx = orow[sidx * 2 + 0];
    float offy = orow[sidx * 2 + 1];

    // fused softmax over the 16 samples of this (r,h)
    float logit = orow[NOFF_ + h * 16 + s];
    float mx = logit;
#pragma unroll
    for (int m = 2; m <= 16; m <<= 1) mx = fmaxf(mx, __shfl_xor_sync(0xffffffffu, mx, m));
    float e = expf(logit - mx);
    float se = e;
#pragma unroll
    for (int m = 2; m <= 16; m <<= 1) se += __shfl_xor_sync(0xffffffffu, se, m);
    float aw = e / se;

    const float* rp = refp + ((size_t)r * 4 + l) * 2;
    float locx = rp[0] + offx / (float)W;
    float locy = rp[1] + offy / (float)H;
    float px = locx * (float)W - 0.5f;
    float py = locy * (float)H - 0.5f;
    float x0f = floorf(px), y0f = floorf(py);
    float fx = px - x0f, fy = py - y0f;
    int x0 = (int)x0f, y0 = (int)y0f;

    float cw00 = (1.f - fx) * (1.f - fy) * aw;
    float cw10 = fx * (1.f - fy) * aw;
    float cw01 = (1.f - fx) * fy * aw;
    float cw11 = fx * fy * aw;

    const float* base = newv + ((size_t)b * LV_ + start) * C_ + h * DH_ + half * 8;

    float acc[8] = {0.f, 0.f, 0.f, 0.f, 0.f, 0.f, 0.f, 0.f};
    auto corner = [&](int xi, int yi, float cw) {
        if ((unsigned)xi < (unsigned)W && (unsigned)yi < (unsigned)H) {
            const float4* vp = (const float4*)(base + ((size_t)yi * W + xi) * C_);
            float4 v0 = vp[0], v1 = vp[1];
            acc[0] += cw * v0.x; acc[1] += cw * v0.y;
            acc[2] += cw * v0.z; acc[3] += cw * v0.w;
            acc[4] += cw * v1.x; acc[5] += cw * v1.y;
            acc[6] += cw * v1.z; acc[7] += cw * v1.w;
        }
    };
    corner(x0,     y0,     cw00);
    corner(x0 + 1, y0,     cw10);
    corner(x0,     y0 + 1, cw01);
    corner(x0 + 1, y0 + 1, cw11);

#pragma unroll
    for (int m = 2; m <= 16; m <<= 1) {
#pragma unroll
        for (int i = 0; i < 8; i++)
            acc[i] += __shfl_xor_sync(0xffffffffu, acc[i], m);
    }

    if (s == 0) {
        float* dst = g_samp + (size_t)r * C_ + h * DH_ + half * 8;
        *(float4*)(dst + 0) = make_float4(acc[0], acc[1], acc[2], acc[3]);
        *(float4*)(dst + 4) = make_float4(acc[4], acc[5], acc[6], acc[7]);
    }
}

// ---------------- launch ----------------
extern "C" void kernel_launch(void* const* d_in, const int* in_sizes, int n_in,
                              void* d_out, int out_size)
{
    const float* query  = (const float*)d_in[0];
    const float* refp   = (const float*)d_in[1];
    const float* value  = (const float*)d_in[2];
    const float* W_off  = (const float*)d_in[5];
    const float* b_off  = (const float*)d_in[6];
    const float* W_attn = (const float*)d_in[7];
    const float* b_attn = (const float*)d_in[8];
    const float* W_val  = (const float*)d_in[9];
    const float* b_val  = (const float*)d_in[10];
    const float* W_out  = (const float*)d_in[11];
    const float* b_out  = (const float*)d_in[12];

    float* NEWQ = (float*)d_out;
    float* NEWV = NEWQ + NEWQ_SIZE_;

    float *p_offatt, *p_samp, *p_bcat;
    uint32_t *p_wb;
    cudaGetSymbolAddress((void**)&p_offatt, g_offatt);
    cudaGetSymbolAddress((void**)&p_samp,   g_samp);
    cudaGetSymbolAddress((void**)&p_bcat,   g_bcat);
    cudaGetSymbolAddress((void**)&p_wb,     g_wb);

    cudaFuncSetAttribute(hmma_gemm, cudaFuncAttributeMaxDynamicSharedMemorySize, VP_SMEM);

    // 1) prep weight images + bias concat
    prep_images<<<5, 256>>>(W_val, W_off, W_attn, W_out);
    concat_bias<<<1, NCAT_>>>(b_off, b_attn);

    // 2) value projection -> new_value (persistent: 3 CTAs/SM x 148 SMs)
    {
        int mtiles = MVAL_ / CTM;               // 13770
        hmma_gemm<<<dim3(444, 1), 128, VP_SMEM>>>(
            value, p_wb, b_val, NEWV, MVAL_, 128, mtiles);
    }

    // 3) offsets + attn logits (3 weight chunks: indices 1..3)
    {
        int mtiles = (NROWS_ + CTM - 1) / CTM;  // 517
        hmma_gemm<<<dim3(mtiles, 3), 128, VP_SMEM>>>(
            query, p_wb + 8192, p_bcat, p_offatt, NROWS_, NCAT_, mtiles);
    }

    // 4) bilinear gather + fused softmax
    gather_kernel<<<NROWS_ * NH_ / 4, 128>>>(NEWV, refp);

    // 5) output projection -> new_query (chunk 4)
    {
        int mtiles = (NROWS_ + CTM - 1) / CTM;
        hmma_gemm<<<dim3(mtiles, 1), 128, VP_SMEM>>>(
            p_samp, p_wb + 4 * 8192, b_out, NEWQ, NROWS_, 128, mtiles);
    }
}